// round 17
// baseline (speedup 1.0000x reference)
#include <cuda_runtime.h>
#include <cstdint>

// Problem shape (fixed per metadata): F_S [16, 64, 256, 256] float32
#define B_   16
#define C_   64
#define HW_  65536            // 256*256
#define HW4_ (HW_/4)          // 16384 float4 per plane
#define EPS_ 1e-12f

// ---- scratch (no allocations allowed) ----
__device__ float         g_a[B_ * C_];        // raw channel means
__device__ unsigned int  g_hist[B_ * 256];    // per-batch histogram
__device__ unsigned char g_q[B_ * HW_];       // quantized cos map

// ------------------------------------------------------------------
// K1: mean over each (b,c) plane + zero histograms. 1024 blocks x 256.
// ------------------------------------------------------------------
__global__ void __launch_bounds__(256) mean_kernel(const float* __restrict__ F) {
    int bc = blockIdx.x;                       // 0..1023
    if (bc < B_) g_hist[bc * 256 + threadIdx.x] = 0u;   // zero hists (before K2)

    const float4* p = reinterpret_cast<const float4*>(F) + (size_t)bc * HW4_;
    float s = 0.f;
    #pragma unroll 4
    for (int i = threadIdx.x; i < HW4_; i += 256) {
        float4 v = p[i];
        s += (v.x + v.y) + (v.z + v.w);
    }
    #pragma unroll
    for (int o = 16; o > 0; o >>= 1) s += __shfl_down_sync(0xffffffffu, s, o);
    __shared__ float sh[8];
    if ((threadIdx.x & 31) == 0) sh[threadIdx.x >> 5] = s;
    __syncthreads();
    if (threadIdx.x == 0) {
        float t = 0.f;
        #pragma unroll
        for (int i = 0; i < 8; i++) t += sh[i];
        g_a[bc] = t * (1.0f / (float)HW_);
    }
}

// ------------------------------------------------------------------
// K2: per-block w = a/||a||, then cos-sim, quantize, histogram.
// grid (HW4_/256, B_), 256 threads.
// ------------------------------------------------------------------
__global__ void __launch_bounds__(256) cos_hist_kernel(const float* __restrict__ F) {
    int b = blockIdx.y;
    int t = threadIdx.x;
    __shared__ unsigned int sh[256];
    __shared__ float sw[C_];
    __shared__ float shn[2];

    sh[t] = 0u;
    // ---- normalization of a (threads 0..63 hold real values) ----
    float av = (t < C_) ? g_a[b * C_ + t] : 0.f;
    float s2 = av * av;
    #pragma unroll
    for (int o = 16; o > 0; o >>= 1) s2 += __shfl_xor_sync(0xffffffffu, s2, o);
    if (t == 0)  shn[0] = s2;     // sum of c=0..31
    if (t == 32) shn[1] = s2;     // sum of c=32..63
    __syncthreads();
    if (t < C_) {
        float n = fmaxf(sqrtf(shn[0] + shn[1]), EPS_);
        sw[t] = av / n;
    }
    __syncthreads();

    int hw4 = blockIdx.x * 256 + t;            // 0..16383
    const float4* base =
        reinterpret_cast<const float4*>(F) + (size_t)b * C_ * HW4_ + hw4;

    float4 dotA = make_float4(0.f, 0.f, 0.f, 0.f);
    float4 ssA  = make_float4(0.f, 0.f, 0.f, 0.f);
    float4 dotB = make_float4(0.f, 0.f, 0.f, 0.f);
    float4 ssB  = make_float4(0.f, 0.f, 0.f, 0.f);
    #pragma unroll 8
    for (int c = 0; c < C_ / 2; c++) {
        float4 v0 = base[(size_t)c * HW4_];
        float4 v1 = base[(size_t)(c + C_ / 2) * HW4_];
        float  w0 = sw[c];
        float  w1 = sw[c + C_ / 2];
        dotA.x += w0 * v0.x;  dotA.y += w0 * v0.y;
        dotA.z += w0 * v0.z;  dotA.w += w0 * v0.w;
        ssA.x  += v0.x * v0.x; ssA.y += v0.y * v0.y;
        ssA.z  += v0.z * v0.z; ssA.w += v0.w * v0.w;
        dotB.x += w1 * v1.x;  dotB.y += w1 * v1.y;
        dotB.z += w1 * v1.z;  dotB.w += w1 * v1.w;
        ssB.x  += v1.x * v1.x; ssB.y += v1.y * v1.y;
        ssB.z  += v1.z * v1.z; ssB.w += v1.w * v1.w;
    }
    float4 dot = make_float4(dotA.x + dotB.x, dotA.y + dotB.y,
                             dotA.z + dotB.z, dotA.w + dotB.w);
    float4 ss  = make_float4(ssA.x + ssB.x, ssA.y + ssB.y,
                             ssA.z + ssB.z, ssA.w + ssB.w);

    int q0 = ((int)((dot.x / fmaxf(sqrtf(ss.x), EPS_)) * 255.0f)) & 255;
    int q1 = ((int)((dot.y / fmaxf(sqrtf(ss.y), EPS_)) * 255.0f)) & 255;
    int q2 = ((int)((dot.z / fmaxf(sqrtf(ss.z), EPS_)) * 255.0f)) & 255;
    int q3 = ((int)((dot.w / fmaxf(sqrtf(ss.w), EPS_)) * 255.0f)) & 255;

    uchar4 qv = make_uchar4((unsigned char)q0, (unsigned char)q1,
                            (unsigned char)q2, (unsigned char)q3);
    *reinterpret_cast<uchar4*>(g_q + (size_t)b * HW_ + (size_t)hw4 * 4) = qv;

    atomicAdd(&sh[q0], 1u);
    atomicAdd(&sh[q1], 1u);
    atomicAdd(&sh[q2], 1u);
    atomicAdd(&sh[q3], 1u);
    __syncthreads();
    {
        unsigned int v = sh[t];
        if (v) atomicAdd(&g_hist[b * 256 + t], v);
    }
}

// ------------------------------------------------------------------
// K4: per-block LUT build (warp-shuffle scan) + apply.
// grid (C_*HW4_/256, B_), 256 threads.
// ------------------------------------------------------------------
__global__ void __launch_bounds__(256) apply_kernel(const float* __restrict__ F,
                                                    float* __restrict__ out) {
    int b = blockIdx.y;
    int t = threadIdx.x;
    int lane = t & 31, wid = t >> 5;
    __shared__ float wsum[8];
    __shared__ float wmin[8];
    __shared__ float slut[256];

    // ---- build LUT from g_hist (identical in every block; deterministic) ----
    float h = (float)g_hist[b * 256 + t];
    // inclusive warp scan
    float x = h;
    #pragma unroll
    for (int o = 1; o < 32; o <<= 1) {
        float y = __shfl_up_sync(0xffffffffu, x, o);
        if (lane >= o) x += y;
    }
    if (lane == 31) wsum[wid] = x;
    __syncthreads();
    // scan the 8 warp sums (every thread does it locally from shared — cheap)
    float prefix = 0.f;
    #pragma unroll
    for (int wcount = 0; wcount < 8; wcount++)
        if (wcount < wid) prefix += wsum[wcount];
    float cdfv = x + prefix;                       // inclusive cdf at bin t
    // min over non-empty bins
    float m = (h > 0.f) ? cdfv : ((float)HW_ + 1.0f);
    #pragma unroll
    for (int o = 16; o > 0; o >>= 1) m = fminf(m, __shfl_xor_sync(0xffffffffu, m, o));
    if (lane == 0) wmin[wid] = m;
    __syncthreads();
    float cdf_min = wmin[0];
    #pragma unroll
    for (int i = 1; i < 8; i++) cdf_min = fminf(cdf_min, wmin[i]);

    float denom = fmaxf((float)HW_ - cdf_min, 1.0f);
    float scale = 255.0f / denom;
    float lutv = rintf((cdfv - cdf_min) * scale);   // round-half-even == jnp.round
    lutv = fminf(fmaxf(lutv, 0.0f), 255.0f);
    slut[t] = lutv * (1.0f / 255.0f);
    __syncthreads();

    // ---- apply ----
    size_t e4 = (size_t)blockIdx.x * 256 + t;       // float4 index within batch
    size_t gidx = (size_t)b * C_ * HW4_ + e4;
    int hw4 = (int)(e4 & (HW4_ - 1));               // hw4 within plane

    float4 v = reinterpret_cast<const float4*>(F)[gidx];
    uchar4 qv = *reinterpret_cast<const uchar4*>(g_q + (size_t)b * HW_ + (size_t)hw4 * 4);

    float4 o;
    o.x = slut[qv.x] * v.x;
    o.y = slut[qv.y] * v.y;
    o.z = slut[qv.z] * v.z;
    o.w = slut[qv.w] * v.w;
    reinterpret_cast<float4*>(out)[gidx] = o;
}

// ------------------------------------------------------------------
extern "C" void kernel_launch(void* const* d_in, const int* in_sizes, int n_in,
                              void* d_out, int out_size) {
    const float* F = (const float*)d_in[0];
    float* out = (float*)d_out;

    mean_kernel<<<B_ * C_, 256>>>(F);
    {
        dim3 g(HW4_ / 256, B_);
        cos_hist_kernel<<<g, 256>>>(F);
    }
    {
        dim3 g((C_ * HW4_) / 256, B_);
        apply_kernel<<<g, 256>>>(F, out);
    }
}